// round 17
// baseline (speedup 1.0000x reference)
#include <cuda_runtime.h>
#include <cuda_fp16.h>
#include <math.h>
#include <stdint.h>

// ---------------- problem constants ----------------
#define Bn 2
#define Ln 2048
#define Dn 512
#define En 768
#define EPSV 1e-6f

// ---------------- scratch (device globals; no allocation) ----------------
__device__ __align__(16) float g_q[Bn * Ln * Dn];      // 8 MB
__device__ __align__(16) float g_k[Bn * Ln * Dn];      // 8 MB
__device__ __align__(16) float g_G[6 * Dn * Dn];       // 6 MB
__device__ __align__(16) float g_T[6 * Ln * Dn];       // 24 MB
__device__ __align__(16) float g_cs[4 * Ln];           // col scales
__device__ __align__(16) float g_csp[4 * 8 * Ln];      // colsum partials

// ---------------- fp16x2 split helpers ----------------
// split2: pack (e, o) = values at (k, k+1) into hi-pair word w0 and lo-pair
// word w1; x = h0 + h1 captures x to ~2^-22 relative.
__device__ __forceinline__ void split2(float e, float o, uint32_t& w0, uint32_t& w1) {
    asm("cvt.rn.f16x2.f32 %0, %1, %2;" : "=r"(w0) : "f"(o), "f"(e));   // lo half = e
    __half2 h = *reinterpret_cast<__half2*>(&w0);
    float e1 = e - __low2float(h);
    float o1 = o - __high2float(h);
    asm("cvt.rn.f16x2.f32 %0, %1, %2;" : "=r"(w1) : "f"(o1), "f"(e1));
}
__device__ __forceinline__ void mma_f16(float* c, const uint32_t* a, const uint32_t* b) {
    asm volatile(
        "mma.sync.aligned.m16n8k16.row.col.f32.f16.f16.f32 "
        "{%0,%1,%2,%3}, {%4,%5,%6,%7}, {%8,%9}, {%0,%1,%2,%3};"
        : "+f"(c[0]), "+f"(c[1]), "+f"(c[2]), "+f"(c[3])
        : "r"(a[0]), "r"(a[1]), "r"(a[2]), "r"(a[3]), "r"(b[0]), "r"(b[1]));
}

// ------ batched fp16x2 (double-half) tensor GEMM, 128x128x16 tiles ---------
// (verbatim from the 796us passing kernel)
struct GB { const float* A[6]; const float* B[6]; float* C[6]; };

template<bool TA, bool TB, bool SYM>
__global__ __launch_bounds__(256, 2)
void mma128(GB gb, int K, int lda, int ldb, int ldc, float bscale, float cscale)
{
    extern __shared__ uint32_t smu[];   // 8192 u32 = 32 KB

    const float* __restrict__ A  = gb.A[blockIdx.z];
    const float* __restrict__ Bm = gb.B[blockIdx.z];
    float* __restrict__ C        = gb.C[blockIdx.z];

    const int tid = threadIdx.x, lane = tid & 31, warp = tid >> 5;
    const int wm = (warp >> 2) * 64, wn = (warp & 3) * 32;   // warp tile 64x32

    int bm, bn;
    if (SYM) {
        int idx = blockIdx.x;                       // triangular index
        bm = (int)((sqrtf(8.0f * idx + 1.0f) - 1.0f) * 0.5f);
        while ((bm + 1) * (bm + 2) / 2 <= idx) bm++;
        while (bm * (bm + 1) / 2 > idx) bm--;
        bn = idx - bm * (bm + 1) / 2;
    } else {
        bm = blockIdx.y; bn = blockIdx.x;
    }
    const int m0 = bm * 128, n0 = bn * 128;

    float acc[4][4][4];
#pragma unroll
    for (int i = 0; i < 4; i++)
#pragma unroll
        for (int j = 0; j < 4; j++)
#pragma unroll
            for (int v = 0; v < 4; v++) acc[i][j][v] = 0.f;

    float4 ra[2], rb[2];

    auto ldgA = [&](int k0) {
        if (!TA) {
            int m = tid & 127, kq0 = tid >> 7;
#pragma unroll
            for (int p = 0; p < 2; p++) {
                int kq = kq0 + p * 2;
                ra[p] = *(const float4*)(A + (size_t)(m0 + m) * lda + k0 + kq * 4);
            }
        } else {
            int k2 = tid >> 5, m4 = (tid & 31) * 4;
            ra[0] = *(const float4*)(A + (size_t)(k0 + 2 * k2)     * lda + m0 + m4);
            ra[1] = *(const float4*)(A + (size_t)(k0 + 2 * k2 + 1) * lda + m0 + m4);
        }
    };
    auto ldgB = [&](int k0) {
        if (TB) {
            int n = tid & 127, kq0 = tid >> 7;
#pragma unroll
            for (int p = 0; p < 2; p++) {
                int kq = kq0 + p * 2;
                rb[p] = *(const float4*)(Bm + (size_t)(n0 + n) * ldb + k0 + kq * 4);
            }
        } else {
            int k2 = tid >> 5, n4 = (tid & 31) * 4;
            rb[0] = *(const float4*)(Bm + (size_t)(k0 + 2 * k2)     * ldb + n0 + n4);
            rb[1] = *(const float4*)(Bm + (size_t)(k0 + 2 * k2 + 1) * ldb + n0 + n4);
        }
    };
    auto stsA = [&](int buf) {
        uint32_t* A0 = smu + buf * 1024;
        uint32_t* A1 = smu + 2048 + buf * 1024;
        if (!TA) {
            int m = tid & 127, kq0 = tid >> 7;
#pragma unroll
            for (int p = 0; p < 2; p++) {
                int kq = kq0 + p * 2;
                float v[4] = {ra[p].x, ra[p].y, ra[p].z, ra[p].w};
#pragma unroll
                for (int j = 0; j < 2; j++) {
                    int k2 = kq * 2 + j;
                    uint32_t w0, w1;
                    split2(v[2 * j], v[2 * j + 1], w0, w1);
                    int idx = k2 * 128 + (m ^ ((k2 & 3) << 3));
                    A0[idx] = w0; A1[idx] = w1;
                }
            }
        } else {
            int k2 = tid >> 5, m4 = (tid & 31) * 4;
            float e[4] = {ra[0].x, ra[0].y, ra[0].z, ra[0].w};
            float o[4] = {ra[1].x, ra[1].y, ra[1].z, ra[1].w};
            uint32_t w0[4], w1[4];
#pragma unroll
            for (int c = 0; c < 4; c++) split2(e[c], o[c], w0[c], w1[c]);
            int idx = k2 * 128 + (m4 ^ ((k2 & 3) << 3));
            *(uint4*)&A0[idx] = make_uint4(w0[0], w0[1], w0[2], w0[3]);
            *(uint4*)&A1[idx] = make_uint4(w1[0], w1[1], w1[2], w1[3]);
        }
    };
    auto stsB = [&](int buf) {
        uint32_t* B0 = smu + 4096 + buf * 1024;
        uint32_t* B1 = smu + 6144 + buf * 1024;
        if (TB) {
            int n = tid & 127, kq0 = tid >> 7;
#pragma unroll
            for (int p = 0; p < 2; p++) {
                int kq = kq0 + p * 2;
                float v[4] = {rb[p].x * bscale, rb[p].y * bscale,
                              rb[p].z * bscale, rb[p].w * bscale};
#pragma unroll
                for (int j = 0; j < 2; j++) {
                    int k2 = kq * 2 + j;
                    uint32_t w0, w1;
                    split2(v[2 * j], v[2 * j + 1], w0, w1);
                    int idx = k2 * 128 + (n ^ ((k2 & 3) << 3));
                    B0[idx] = w0; B1[idx] = w1;
                }
            }
        } else {
            int k2 = tid >> 5, n4 = (tid & 31) * 4;
            float e[4] = {rb[0].x * bscale, rb[0].y * bscale, rb[0].z * bscale, rb[0].w * bscale};
            float o[4] = {rb[1].x * bscale, rb[1].y * bscale, rb[1].z * bscale, rb[1].w * bscale};
            uint32_t w0[4], w1[4];
#pragma unroll
            for (int c = 0; c < 4; c++) split2(e[c], o[c], w0[c], w1[c]);
            int idx = k2 * 128 + (n4 ^ ((k2 & 3) << 3));
            *(uint4*)&B0[idx] = make_uint4(w0[0], w0[1], w0[2], w0[3]);
            *(uint4*)&B1[idx] = make_uint4(w1[0], w1[1], w1[2], w1[3]);
        }
    };
    auto compute = [&](int buf) {
        const uint32_t* A0 = smu + buf * 1024;
        const uint32_t* A1 = smu + 2048 + buf * 1024;
        const uint32_t* B0 = smu + 4096 + buf * 1024;
        const uint32_t* B1 = smu + 6144 + buf * 1024;
        const int kp = lane & 3, sw = kp << 3, g = lane >> 2;
        uint32_t a0f[4][4], a1f[4][4];
#pragma unroll
        for (int i = 0; i < 4; i++) {
            int r = wm + i * 16 + g;
            int i0 = kp * 128 + (r ^ sw);
            int i1 = kp * 128 + ((r + 8) ^ sw);
            int i2 = (kp + 4) * 128 + (r ^ sw);
            int i3 = (kp + 4) * 128 + ((r + 8) ^ sw);
            a0f[i][0] = A0[i0]; a0f[i][1] = A0[i1]; a0f[i][2] = A0[i2]; a0f[i][3] = A0[i3];
            a1f[i][0] = A1[i0]; a1f[i][1] = A1[i1]; a1f[i][2] = A1[i2]; a1f[i][3] = A1[i3];
        }
#pragma unroll
        for (int j = 0; j < 4; j++) {
            int n = wn + j * 8 + g;
            uint32_t b0[2], b1[2];
            b0[0] = B0[kp * 128 + (n ^ sw)];
            b0[1] = B0[(kp + 4) * 128 + (n ^ sw)];
            b1[0] = B1[kp * 128 + (n ^ sw)];
            b1[1] = B1[(kp + 4) * 128 + (n ^ sw)];
#pragma unroll
            for (int i = 0; i < 4; i++) {
                mma_f16(acc[i][j], a1f[i], b0);   // small terms first
                mma_f16(acc[i][j], a0f[i], b1);
                mma_f16(acc[i][j], a0f[i], b0);
            }
        }
    };

    const int nt = K >> 4;
    ldgA(0); ldgB(0); stsA(0); stsB(0);
    __syncthreads();
#pragma unroll 1
    for (int t = 0; t < nt; t++) {
        int buf = t & 1;
        if (t + 1 < nt) { ldgA((t + 1) << 4); ldgB((t + 1) << 4); }
        compute(buf);
        if (t + 1 < nt) { stsA(buf ^ 1); stsB(buf ^ 1); __syncthreads(); }
    }

#pragma unroll
    for (int i = 0; i < 4; i++) {
        int r = m0 + wm + i * 16 + (lane >> 2);
#pragma unroll
        for (int j = 0; j < 4; j++) {
            int cN = n0 + wn + j * 8 + (lane & 3) * 2;
            float v0 = acc[i][j][0] * cscale, v1 = acc[i][j][1] * cscale;
            float v2 = acc[i][j][2] * cscale, v3 = acc[i][j][3] * cscale;
            *(float2*)&C[(size_t)r * ldc + cN]       = make_float2(v0, v1);
            *(float2*)&C[(size_t)(r + 8) * ldc + cN] = make_float2(v2, v3);
            if (SYM && bm != bn) {                      // mirror write C[j][i]
                C[(size_t)cN * ldc + r]           = v0;
                C[(size_t)(cN + 1) * ldc + r]     = v1;
                C[(size_t)cN * ldc + r + 8]       = v2;
                C[(size_t)(cN + 1) * ldc + r + 8] = v3;
            }
        }
    }
}

// ---------------- warp reductions ----------------
__device__ __forceinline__ float warp_sum_f(float v) {
#pragma unroll
    for (int o = 16; o; o >>= 1) v += __shfl_xor_sync(0xffffffffu, v, o);
    return v;
}
__device__ __forceinline__ float warp_max_f(float v) {
#pragma unroll
    for (int o = 16; o; o >>= 1) v = fmaxf(v, __shfl_xor_sync(0xffffffffu, v, o));
    return v;
}

// Newton solve for 1.5-entmax threshold over a warp-held row (64 vals/lane):
// sum(max(z - tau, 0)^2) = 1; z halved and max-subtracted (max(z) == 0).
// Convex decreasing; Newton from tau=-1 converges monotonically from the left.
__device__ float entmax_tau_warp64(const float z[64]) {
    float tau = -1.0f;
#pragma unroll 1
    for (int it = 0; it < 50; it++) {
        float s1 = 0.f, s2 = 0.f;
#pragma unroll
        for (int j = 0; j < 64; j++) {
            float d = fmaxf(z[j] - tau, 0.f);
            s1 += d; s2 = fmaf(d, d, s2);
        }
#pragma unroll
        for (int o = 16; o; o >>= 1) {
            s1 += __shfl_xor_sync(0xffffffffu, s1, o);
            s2 += __shfl_xor_sync(0xffffffffu, s2, o);
        }
        if (s1 <= 0.f) break;
        float dt = (s2 - 1.0f) / (2.0f * s1);
        tau += dt;
        if (dt <= 1e-8f) break;
    }
    return tau;
}

// ---------------- LayerNorm + RoPE (in place on g_q / g_k) ----------------
__global__ __launch_bounds__(128)
void lnrope_kernel(float* __restrict__ q, float* __restrict__ k,
                   const float* __restrict__ qg, const float* __restrict__ qb,
                   const float* __restrict__ kg, const float* __restrict__ kb)
{
    __shared__ float sred[4];
    int row = blockIdx.x;
    int t = row & (Ln - 1);
    float* base = (blockIdx.y ? k : q) + (size_t)row * Dn;
    const float* gamma = blockIdx.y ? kg : qg;
    const float* beta  = blockIdx.y ? kb : qb;
    int tid = threadIdx.x;

    float v0 = base[tid], v1 = base[tid + 128], v2 = base[tid + 256], v3 = base[tid + 384];
    float s = warp_sum_f(v0 + v1 + v2 + v3);
    if ((tid & 31) == 0) sred[tid >> 5] = s;
    __syncthreads();
    float mu = (sred[0] + sred[1] + sred[2] + sred[3]) * (1.0f / 512.0f);
    float d0 = v0 - mu, d1 = v1 - mu, d2 = v2 - mu, d3 = v3 - mu;
    float sq = warp_sum_f(d0*d0 + d1*d1 + d2*d2 + d3*d3);
    __syncthreads();
    if ((tid & 31) == 0) sred[tid >> 5] = sq;
    __syncthreads();
    float var = (sred[0] + sred[1] + sred[2] + sred[3]) * (1.0f / 512.0f);
    float rs = rsqrtf(var + 1e-5f);

    float n0 = d0 * rs * gamma[tid]       + beta[tid];
    float n1 = d1 * rs * gamma[tid + 128] + beta[tid + 128];
    float n2 = d2 * rs * gamma[tid + 256] + beta[tid + 256];
    float n3 = d3 * rs * gamma[tid + 384] + beta[tid + 384];

    const double lg = 9.210340371976184 / 256.0;   // log(10000)/256
    float inv0 = (float)exp(-(double)tid * lg);
    float inv1 = (float)exp(-(double)(tid + 128) * lg);
    float ft = (float)t;
    float a0 = ft * inv0, a1 = ft * inv1;
    float c0 = cosf(a0), s0 = sinf(a0);
    float c1 = cosf(a1), s1 = sinf(a1);
    base[tid]       = n0 * c0 - n2 * s0;
    base[tid + 256] = n2 * c0 + n0 * s0;
    base[tid + 128] = n1 * c1 - n3 * s1;
    base[tid + 384] = n3 * c1 + n1 * s1;
}

// ------- warp-per-row: center + scale + entmax + clip (slots 1..3) --------
__global__ __launch_bounds__(256)
void entmax_p_kernel(float* __restrict__ out,
                     const float* __restrict__ Cw, const float* __restrict__ Fw,
                     const float* __restrict__ Sw)
{
    int warp = threadIdx.x >> 5, lane = threadIdx.x & 31;
    int row = blockIdx.x * 8 + warp;
    int b = blockIdx.y, mat = blockIdx.z;
    size_t LL = (size_t)Ln * Ln;
    float* base = out + ((size_t)((mat + 1) * Bn + b)) * LL + (size_t)row * Ln;
    const float* wp = (mat == 0) ? Cw : (mat == 1 ? Fw : Sw);
    float w = 2.0f / (1.0f + expf(-wp[0]));

    float z[64];
#pragma unroll
    for (int i = 0; i < 64; i++) z[i] = base[lane + 32 * i];

    float s = 0.f;
#pragma unroll
    for (int i = 0; i < 64; i++) s += z[i];
    s = warp_sum_f(s);
    float mu = s * (1.0f / 2048.0f);

    float hw = 0.5f * w;
    float m = -3.4e38f;
#pragma unroll
    for (int i = 0; i < 64; i++) { z[i] = (z[i] - mu) * hw; m = fmaxf(m, z[i]); }
    m = warp_max_f(m);
#pragma unroll
    for (int i = 0; i < 64; i++) z[i] -= m;

    float tau = entmax_tau_warp64(z);
#pragma unroll
    for (int i = 0; i < 64; i++) {
        float d = fmaxf(z[i] - tau, 0.f);
        base[lane + 32 * i] = fminf(d * d, 1.0f - EPSV);
    }
}

// ---------------- column sums (two-phase) ----------------
__global__ __launch_bounds__(256)
void colsum_part_kernel(const float* __restrict__ out)
{
    int j = blockIdx.x * 256 + threadIdx.x;
    int b = blockIdx.y;
    int chunk = blockIdx.z & 7;
    int m = blockIdx.z >> 3;
    size_t LL = (size_t)Ln * Ln;
    const float* base = out + ((size_t)((m ? 3 : 1) * Bn + b)) * LL + (size_t)chunk * 256 * Ln + j;
    float s = 0.f;
#pragma unroll 8
    for (int i = 0; i < 256; i++) s += base[(size_t)i * Ln];
    g_csp[(((m * Bn + b) * 8) + chunk) * Ln + j] = s;
}
__global__ __launch_bounds__(256)
void colsum_fin_kernel()
{
    int j = blockIdx.x * 256 + threadIdx.x;
    int slot = blockIdx.y;
    float s = 0.f;
#pragma unroll
    for (int c = 0; c < 8; c++) s += g_csp[(slot * 8 + c) * Ln + j];
    g_cs[slot * Ln + j] = rsqrtf(s + EPSV);
}

// ----- warp-per-row finalize: col-scale + EPS affine + sparse-log H --------
// Support bound: tau* >= z_max - 1 for entmax15, so any element with product
// w <= w_max * e^-6 is provably outside support and contributes 0 to the
// Newton root -> compute log only above thresh = w_max * 2e-3 (< e^-6).
__global__ __launch_bounds__(256)
void finalize_kernel(float* __restrict__ out)
{
    int warp = threadIdx.x >> 5, lane = threadIdx.x & 31;
    int row = blockIdx.x * 8 + warp;
    int b = blockIdx.y;
    size_t LL = (size_t)Ln * Ln;
    float* pH = out + ((size_t)(0 * Bn + b)) * LL + (size_t)row * Ln;
    float* pC = out + ((size_t)(1 * Bn + b)) * LL + (size_t)row * Ln;
    float* pF = out + ((size_t)(2 * Bn + b)) * LL + (size_t)row * Ln;
    float* pS = out + ((size_t)(3 * Bn + b)) * LL + (size_t)row * Ln;
    const float Aa = 1.0f - 2.0f * EPSV;

    float h[64];
    float wmax = 0.f;
#pragma unroll
    for (int i = 0; i < 64; i++) {
        int j = lane + 32 * i;
        float csC = g_cs[(0 * Bn + b) * Ln + j];
        float csS = g_cs[(1 * Bn + b) * Ln + j];
        float c = fmaf(pC[j] * csC, Aa, EPSV);
        float f = fmaf(pF[j],       Aa, EPSV);
        float s = fmaf(pS[j] * csS, Aa, EPSV);
        pC[j] = c; pF[j] = f; pS[j] = s;
        float wv = c * f * s;                       // in [1e-18, 1]
        if (j == row) wv = 0.f;                     // diag mask (-inf in log)
        h[i] = wv;
        wmax = fmaxf(wmax, wv);
    }
    wmax = warp_max_f(wmax);
    float thresh = wmax * 2.0e-3f;                  // < e^-6 * wmax (safe)

    // z = log(w)/6 for candidates (== (log/3) then *0.5), else -inf proxy
    float m = -3.4e38f;
#pragma unroll
    for (int i = 0; i < 64; i++) {
        h[i] = (h[i] > thresh) ? __logf(h[i]) * (1.0f / 6.0f) : -1e9f;
        m = fmaxf(m, h[i]);
    }
    m = warp_max_f(m);
#pragma unroll
    for (int i = 0; i < 64; i++) h[i] -= m;

    float tau = entmax_tau_warp64(h);
#pragma unroll
    for (int i = 0; i < 64; i++) {
        float d = fmaxf(h[i] - tau, 0.f);
        pH[lane + 32 * i] = d * d;
    }
}

// ---------------- launch ----------------
extern "C" void kernel_launch(void* const* d_in, const int* in_sizes, int n_in,
                              void* d_out, int out_size)
{
    const float* x  = (const float*)d_in[0];
    const float* Wq = (const float*)d_in[1];
    const float* Wk = (const float*)d_in[2];
    const float* qg = (const float*)d_in[3];
    const float* qb = (const float*)d_in[4];
    const float* kg = (const float*)d_in[5];
    const float* kb = (const float*)d_in[6];
    const float* Cw = (const float*)d_in[7];
    const float* Fw = (const float*)d_in[8];
    const float* Sw = (const float*)d_in[9];
    float* out = (float*)d_out;

    float *q, *k, *G, *T;
    cudaGetSymbolAddress((void**)&q, g_q);
    cudaGetSymbolAddress((void**)&k, g_k);
    cudaGetSymbolAddress((void**)&G, g_G);
    cudaGetSymbolAddress((void**)&T, g_T);

    const size_t LL = (size_t)Ln * Ln, LD = (size_t)Ln * Dn, DD = (size_t)Dn * Dn;
    const int SMEM = 32 * 1024;

    // 1) projections: q_pre = x @ Wq^T, k_pre = x @ Wk^T   (M=4096, N=512, K=768)
    {
        GB gb{};
        gb.A[0] = x; gb.B[0] = Wq; gb.C[0] = q;
        gb.A[1] = x; gb.B[1] = Wk; gb.C[1] = k;
        mma128<false, true, false><<<dim3(Dn / 128, (Bn * Ln) / 128, 2), 256, SMEM>>>(
            gb, En, En, En, Dn, 32.0f, 1.0f / 32.0f);
    }

    // 2) LayerNorm + RoPE in place
    lnrope_kernel<<<dim3(Bn * Ln, 2), 128>>>(q, k, qg, qb, kg, kb);

    // 3) Gram matrices: G[d][e] = sum_l A[l,d] B[l,e]   (M=N=512, K=2048, TA)
    {
        GB gb{};
        for (int b = 0; b < 2; b++) {
            gb.A[0 + b] = k + b * LD; gb.B[0 + b] = k + b * LD; gb.C[0 + b] = G + (0 + b) * DD;
            gb.A[2 + b] = k + b * LD; gb.B[2 + b] = q + b * LD; gb.C[2 + b] = G + (2 + b) * DD;
            gb.A[4 + b] = q + b * LD; gb.B[4 + b] = q + b * LD; gb.C[4 + b] = G + (4 + b) * DD;
        }
        mma128<true, false, false><<<dim3(Dn / 128, Dn / 128, 6), 256, SMEM>>>(
            gb, Ln, Dn, Dn, Dn, 1.0f, 1.0f);
    }

    // 4) T = U @ G   (M=2048, N=512, K=512)
    {
        GB gb{};
        for (int b = 0; b < 2; b++) {
            gb.A[0 + b] = q + b * LD; gb.B[0 + b] = G + (0 + b) * DD; gb.C[0 + b] = T + (0 + b) * LD;
            gb.A[2 + b] = q + b * LD; gb.B[2 + b] = G + (2 + b) * DD; gb.C[2 + b] = T + (2 + b) * LD;
            gb.A[4 + b] = k + b * LD; gb.B[4 + b] = G + (4 + b) * DD; gb.C[4 + b] = T + (4 + b) * LD;
        }
        mma128<false, false, false><<<dim3(Dn / 128, Ln / 128, 6), 256, SMEM>>>(
            gb, Dn, Dn, Dn, Dn, 1.0f, 1.0f);
    }

    // 5a) symmetric raw: C_raw = Tc @ q^T, S_raw = Ts @ k^T (triangle + mirror)
    {
        GB gb{};
        for (int b = 0; b < 2; b++) {
            gb.A[0 + b] = T + (0 + b) * LD; gb.B[0 + b] = q + b * LD; gb.C[0 + b] = out + (size_t)(1 * Bn + b) * LL;
            gb.A[2 + b] = T + (4 + b) * LD; gb.B[2 + b] = k + b * LD; gb.C[2 + b] = out + (size_t)(3 * Bn + b) * LL;
        }
        const int NT = (Ln / 128) * (Ln / 128 + 1) / 2;   // 136 triangular tiles
        mma128<false, true, true><<<dim3(NT, 1, 4), 256, SMEM>>>(
            gb, Dn, Dn, Dn, Ln, 1.0f, 1.0f);
    }
    // 5b) F_raw = Tf @ k^T (full)
    {
        GB gb{};
        for (int b = 0; b < 2; b++) {
            gb.A[b] = T + (2 + b) * LD; gb.B[b] = k + b * LD; gb.C[b] = out + (size_t)(2 * Bn + b) * LL;
        }
        mma128<false, true, false><<<dim3(Ln / 128, Ln / 128, 2), 256, SMEM>>>(
            gb, Dn, Dn, Dn, Ln, 1.0f, 1.0f);
    }

    // 6) warp-per-row entmax, 7) column scales (2-phase), 8) warp finalize + H
    entmax_p_kernel<<<dim3(Ln / 8, Bn, 3), 256>>>(out, Cw, Fw, Sw);
    colsum_part_kernel<<<dim3(Ln / 256, Bn, 16), 256>>>(out);
    colsum_fin_kernel<<<dim3(Ln / 256, 4), 256>>>();
    finalize_kernel<<<dim3(Ln / 8, Bn), 256>>>(out);
}